// round 8
// baseline (speedup 1.0000x reference)
#include <cuda_runtime.h>

// ---------------------------------------------------------------------------
// AuxSeLoss: loss = mean(bce(out0,t)) + 0.4*mean(bce(out1,t)) + 0.2*mean(bce(out2, se_t))
// se_t[b,c] = 1 if any element of targets[b] falls in histc bin c (21 bins over [0,20]).
// Shapes: out0/out1/targets [16,21,256,256] f32, out2 [16,21] f32, output scalar f32.
//
// Single fused kernel, exactly ONE resident wave:
//   GRID = 1184 = 148 SMs x 8 blocks (8 blocks x 8 warps = 64-warp/SM cap)
//        = 16 batches x 74 blocks.
// Each batch is 1344 groups of 256 float4; block bInBatch processes groups
// g = it*74 + bInBatch for it in [0,18), plus a predicated 19th iteration for
// bInBatch < 12 (74*18 + 12 = 1344, exact cover). One batch per block keeps
// the histogram-flag logic branch-free. R7 profile showed 1.51 waves (grid
// 1792 vs 1184 resident) capping DRAM at 65%; this removes the partial wave.
// ---------------------------------------------------------------------------

namespace {
constexpr int   NC            = 21;
constexpr int   NB            = 16;
constexpr long long HW        = 256LL * 256LL;
constexpr long long CHW       = (long long)NC * HW;     // 1376256
constexpr long long NTOT      = (long long)NB * CHW;    // 22020096
constexpr int   V4_PER_BATCH  = (int)(CHW / 4);         // 344064
constexpr int   BLK_PER_BATCH = 74;
constexpr int   GRID          = NB * BLK_PER_BATCH;     // 1184 = 148*8
constexpr int   THREADS       = 256;
constexpr int   NWARP         = THREADS / 32;
constexpr int   GROUPS        = V4_PER_BATCH / THREADS; // 1344 groups of 256 v4
constexpr int   FULL_ITERS    = GROUPS / BLK_PER_BATCH; // 18
constexpr int   EXTRA_BLKS    = GROUPS % BLK_PER_BATCH; // 12
static_assert(FULL_ITERS * BLK_PER_BATCH + EXTRA_BLKS == GROUPS, "");
}

__device__ float        g_part0[GRID];
__device__ float        g_part1[GRID];
__device__ unsigned int g_flagp[GRID];
__device__ unsigned int g_count;          // zero at load; reset by finalizer

__device__ __forceinline__ float bce_term(float x, float t) {
    // max(x,0) - x*t + log1p(exp(-|x|)) with HW EX2/LG2 intrinsics.
    float e = __expf(-fabsf(x));
    return fmaxf(x, 0.0f) - x * t + __logf(1.0f + e);
}

__global__ __launch_bounds__(THREADS) void fused_kernel(
    const float4* __restrict__ o0,
    const float4* __restrict__ o1,
    const float4* __restrict__ tg,
    const float*  __restrict__ o2,
    float*        __restrict__ out) {

    __shared__ unsigned int flagS;
    __shared__ float red0[NWARP];
    __shared__ float red1[NWARP];
    __shared__ int   isLastS;

    const int tid  = (int)threadIdx.x;
    const int lane = tid & 31;
    const int wid  = tid >> 5;
    if (tid == 0) flagS = 0u;
    __syncthreads();

    const int blk      = (int)blockIdx.x;
    const int batch    = blk / BLK_PER_BATCH;
    const int bInBatch = blk - batch * BLK_PER_BATCH;
    // group g -> v4 index = batch*V4_PER_BATCH + g*THREADS + tid
    const int base = batch * V4_PER_BATCH + bInBatch * THREADS + tid;

    float s0a = 0.0f, s0b = 0.0f, s1a = 0.0f, s1b = 0.0f;
    unsigned int seen = 0u;
    const float inv_bw = 21.0f / 20.0f;   // 1 / ((n_classes-1)/n_classes)

    #pragma unroll 6
    for (int it = 0; it <= FULL_ITERS; ++it) {
        if (it == FULL_ITERS && bInBatch >= EXTRA_BLKS) break;
        const int i = base + it * (BLK_PER_BATCH * THREADS);
        float4 a  = __ldcs(&o0[i]);
        float4 b4 = __ldcs(&o1[i]);
        float4 t4 = __ldcs(&tg[i]);

        s0a += bce_term(a.x,  t4.x) + bce_term(a.y,  t4.y);
        s0b += bce_term(a.z,  t4.z) + bce_term(a.w,  t4.w);
        s1a += bce_term(b4.x, t4.x) + bce_term(b4.y, t4.y);
        s1b += bce_term(b4.z, t4.z) + bce_term(b4.w, t4.w);

        float tv[4] = {t4.x, t4.y, t4.z, t4.w};
        #pragma unroll
        for (int k = 0; k < 4; ++k) {
            float v = tv[k];
            if (v >= 0.0f && v <= 20.0f) {            // histc drops out-of-range
                int idx = (int)floorf(v * inv_bw);
                idx = min(max(idx, 0), NC - 1);
                seen |= 1u << idx;
            }
        }
    }

    float s0 = s0a + s0b;
    float s1 = s1a + s1b;

    #pragma unroll
    for (int off = 16; off > 0; off >>= 1) {
        s0   += __shfl_down_sync(0xffffffffu, s0, off);
        s1   += __shfl_down_sync(0xffffffffu, s1, off);
        seen |= __shfl_down_sync(0xffffffffu, seen, off);
    }
    if (lane == 0) {
        red0[wid] = s0;
        red1[wid] = s1;
        if (seen) atomicOr(&flagS, seen);
    }
    __syncthreads();

    if (tid == 0) {
        s0 = red0[0]; s1 = red1[0];
        #pragma unroll
        for (int w = 1; w < NWARP; ++w) { s0 += red0[w]; s1 += red1[w]; }
        // L2-coherent publish (no SM ever holds these lines stale in L1)
        __stcg(&g_part0[blk], s0);
        __stcg(&g_part1[blk], s1);
        __stcg(&g_flagp[blk], flagS);
        __threadfence();                               // order publishes before count
        unsigned int prev = atomicAdd(&g_count, 1u);
        isLastS = (prev == (unsigned int)(GRID - 1));
        if (isLastS) atomicExch(&g_count, 0u);         // reset for next replay
    }
    __syncthreads();
    if (!isLastS) return;

    // ---------------- last block: finalize ----------------
    __threadfence();   // acquire side of the counter handshake

    __shared__ unsigned int flagsF[NB];
    __shared__ double redD[NWARP];
    __shared__ float  redF[NWARP];
    if (tid < NB) flagsF[tid] = 0u;
    __syncthreads();

    double d01 = 0.0;                 // s0 + 0.4*s1 folded
    #pragma unroll
    for (int i = tid; i < GRID; i += THREADS) {
        d01 += (double)__ldcg(&g_part0[i]) + 0.4 * (double)__ldcg(&g_part1[i]);
        unsigned int f = __ldcg(&g_flagp[i]);
        if (f) atomicOr(&flagsF[i / BLK_PER_BATCH], f);
    }
    #pragma unroll
    for (int off = 16; off > 0; off >>= 1)
        d01 += __shfl_down_sync(0xffffffffu, d01, off);
    if (lane == 0) redD[wid] = d01;
    __syncthreads();                  // also publishes flagsF

    // se BCE over ALL 336 out2 elements (strided; THREADS < 336)
    float v = 0.0f;
    for (int i = tid; i < NB * NC; i += THREADS) {
        int b = i / NC;
        int c = i - b * NC;
        float t = ((flagsF[b] >> c) & 1u) ? 1.0f : 0.0f;
        float x = o2[i];
        v += fmaxf(x, 0.0f) - x * t + log1pf(expf(-fabsf(x)));
    }
    #pragma unroll
    for (int off = 16; off > 0; off >>= 1)
        v += __shfl_down_sync(0xffffffffu, v, off);
    if (lane == 0) redF[wid] = v;
    __syncthreads();

    if (tid == 0) {
        double dd = 0.0; float vv = 0.0f;
        #pragma unroll
        for (int w = 0; w < NWARP; ++w) { dd += redD[w]; vv += redF[w]; }
        double loss01  = dd / (double)NTOT;
        double loss_se = (double)vv / (double)(NB * NC);
        out[0] = (float)(loss01 + 0.2 * loss_se);
    }
}

extern "C" void kernel_launch(void* const* d_in, const int* in_sizes, int n_in,
                              void* d_out, int out_size) {
    (void)in_sizes; (void)n_in; (void)out_size;
    const float4* o0 = (const float4*)d_in[0];
    const float4* o1 = (const float4*)d_in[1];
    const float*  o2 = (const float*) d_in[2];
    const float4* tg = (const float4*)d_in[3];

    fused_kernel<<<GRID, THREADS>>>(o0, o1, tg, o2, (float*)d_out);
}

// round 9
// speedup vs baseline: 1.1295x; 1.1295x over previous
#include <cuda_runtime.h>

// ---------------------------------------------------------------------------
// AuxSeLoss: loss = mean(bce(out0,t)) + 0.4*mean(bce(out1,t)) + 0.2*mean(bce(out2, se_t))
// se_t[b,c] = 1 if any element of targets[b] falls in histc bin c (21 bins over [0,20]).
// Shapes: out0/out1/targets [16,21,256,256] f32, out2 [16,21] f32, output scalar f32.
//
// Single fused kernel, exactly ONE resident wave -- for real this time:
// R8 compiled to 36 regs -> only 7 blocks/SM resident -> GRID=1184 ran as
// 1.14 waves (full wave + 13% straggler tail), regressing to 55.8us.
// __launch_bounds__(256, 8) forces the 32-reg budget so 8 blocks/SM = 64
// warps actually fit and 1184 blocks = one exact wave. Register diet to
// avoid spills: 2 accumulators, unroll 2 (MLP is not the limiter here),
// truncation cast instead of floorf in the histogram.
// ---------------------------------------------------------------------------

namespace {
constexpr int   NC            = 21;
constexpr int   NB            = 16;
constexpr long long HW        = 256LL * 256LL;
constexpr long long CHW       = (long long)NC * HW;     // 1376256
constexpr long long NTOT      = (long long)NB * CHW;    // 22020096
constexpr int   V4_PER_BATCH  = (int)(CHW / 4);         // 344064
constexpr int   BLK_PER_BATCH = 74;
constexpr int   GRID          = NB * BLK_PER_BATCH;     // 1184 = 148*8
constexpr int   THREADS       = 256;
constexpr int   NWARP         = THREADS / 32;
constexpr int   GROUPS        = V4_PER_BATCH / THREADS; // 1344 groups of 256 v4
constexpr int   FULL_ITERS    = GROUPS / BLK_PER_BATCH; // 18
constexpr int   EXTRA_BLKS    = GROUPS % BLK_PER_BATCH; // 12
static_assert(FULL_ITERS * BLK_PER_BATCH + EXTRA_BLKS == GROUPS, "");
}

__device__ float        g_part0[GRID];
__device__ float        g_part1[GRID];
__device__ unsigned int g_flagp[GRID];
__device__ unsigned int g_count;          // zero at load; reset by finalizer

__device__ __forceinline__ float bce_term(float x, float t) {
    // max(x,0) - x*t + log1p(exp(-|x|)) with HW EX2/LG2 intrinsics.
    float e = __expf(-fabsf(x));
    return fmaxf(x, 0.0f) - x * t + __logf(1.0f + e);
}

__global__ __launch_bounds__(THREADS, 8) void fused_kernel(
    const float4* __restrict__ o0,
    const float4* __restrict__ o1,
    const float4* __restrict__ tg,
    const float*  __restrict__ o2,
    float*        __restrict__ out) {

    __shared__ unsigned int flagS;
    __shared__ float red0[NWARP];
    __shared__ float red1[NWARP];
    __shared__ int   isLastS;

    const int tid  = (int)threadIdx.x;
    const int lane = tid & 31;
    const int wid  = tid >> 5;
    if (tid == 0) flagS = 0u;
    __syncthreads();

    const int blk      = (int)blockIdx.x;
    const int batch    = blk / BLK_PER_BATCH;
    const int bInBatch = blk - batch * BLK_PER_BATCH;
    // group g -> v4 index = batch*V4_PER_BATCH + g*THREADS + tid
    const int base = batch * V4_PER_BATCH + bInBatch * THREADS + tid;

    float s0 = 0.0f, s1 = 0.0f;
    unsigned int seen = 0u;
    const float inv_bw = 21.0f / 20.0f;   // 1 / ((n_classes-1)/n_classes)

    #pragma unroll 2
    for (int it = 0; it <= FULL_ITERS; ++it) {
        if (it == FULL_ITERS && bInBatch >= EXTRA_BLKS) break;
        const int i = base + it * (BLK_PER_BATCH * THREADS);
        float4 a  = __ldcs(&o0[i]);
        float4 b4 = __ldcs(&o1[i]);
        float4 t4 = __ldcs(&tg[i]);

        s0 += bce_term(a.x,  t4.x) + bce_term(a.y,  t4.y)
            + bce_term(a.z,  t4.z) + bce_term(a.w,  t4.w);
        s1 += bce_term(b4.x, t4.x) + bce_term(b4.y, t4.y)
            + bce_term(b4.z, t4.z) + bce_term(b4.w, t4.w);

        float tv[4] = {t4.x, t4.y, t4.z, t4.w};
        #pragma unroll
        for (int k = 0; k < 4; ++k) {
            float v = tv[k];
            if (v >= 0.0f && v <= 20.0f) {            // histc drops out-of-range
                int idx = min((int)(v * inv_bw), NC - 1);   // trunc == floor for v>=0
                seen |= 1u << idx;
            }
        }
    }

    #pragma unroll
    for (int off = 16; off > 0; off >>= 1) {
        s0   += __shfl_down_sync(0xffffffffu, s0, off);
        s1   += __shfl_down_sync(0xffffffffu, s1, off);
        seen |= __shfl_down_sync(0xffffffffu, seen, off);
    }
    if (lane == 0) {
        red0[wid] = s0;
        red1[wid] = s1;
        if (seen) atomicOr(&flagS, seen);
    }
    __syncthreads();

    if (tid == 0) {
        s0 = red0[0]; s1 = red1[0];
        #pragma unroll
        for (int w = 1; w < NWARP; ++w) { s0 += red0[w]; s1 += red1[w]; }
        // L2-coherent publish (no SM ever holds these lines stale in L1)
        __stcg(&g_part0[blk], s0);
        __stcg(&g_part1[blk], s1);
        __stcg(&g_flagp[blk], flagS);
        __threadfence();                               // order publishes before count
        unsigned int prev = atomicAdd(&g_count, 1u);
        isLastS = (prev == (unsigned int)(GRID - 1));
        if (isLastS) atomicExch(&g_count, 0u);         // reset for next replay
    }
    __syncthreads();
    if (!isLastS) return;

    // ---------------- last block: finalize ----------------
    __threadfence();   // acquire side of the counter handshake

    __shared__ unsigned int flagsF[NB];
    __shared__ double redD[NWARP];
    __shared__ float  redF[NWARP];
    if (tid < NB) flagsF[tid] = 0u;
    __syncthreads();

    double d01 = 0.0;                 // s0 + 0.4*s1 folded
    #pragma unroll
    for (int i = tid; i < GRID; i += THREADS) {
        d01 += (double)__ldcg(&g_part0[i]) + 0.4 * (double)__ldcg(&g_part1[i]);
        unsigned int f = __ldcg(&g_flagp[i]);
        if (f) atomicOr(&flagsF[i / BLK_PER_BATCH], f);
    }
    #pragma unroll
    for (int off = 16; off > 0; off >>= 1)
        d01 += __shfl_down_sync(0xffffffffu, d01, off);
    if (lane == 0) redD[wid] = d01;
    __syncthreads();                  // also publishes flagsF

    // se BCE over ALL 336 out2 elements (strided; THREADS < 336)
    float v = 0.0f;
    for (int i = tid; i < NB * NC; i += THREADS) {
        int b = i / NC;
        int c = i - b * NC;
        float t = ((flagsF[b] >> c) & 1u) ? 1.0f : 0.0f;
        float x = o2[i];
        v += fmaxf(x, 0.0f) - x * t + log1pf(expf(-fabsf(x)));
    }
    #pragma unroll
    for (int off = 16; off > 0; off >>= 1)
        v += __shfl_down_sync(0xffffffffu, v, off);
    if (lane == 0) redF[wid] = v;
    __syncthreads();

    if (tid == 0) {
        double dd = 0.0; float vv = 0.0f;
        #pragma unroll
        for (int w = 0; w < NWARP; ++w) { dd += redD[w]; vv += redF[w]; }
        double loss01  = dd / (double)NTOT;
        double loss_se = (double)vv / (double)(NB * NC);
        out[0] = (float)(loss01 + 0.2 * loss_se);
    }
}

extern "C" void kernel_launch(void* const* d_in, const int* in_sizes, int n_in,
                              void* d_out, int out_size) {
    (void)in_sizes; (void)n_in; (void)out_size;
    const float4* o0 = (const float4*)d_in[0];
    const float4* o1 = (const float4*)d_in[1];
    const float*  o2 = (const float*) d_in[2];
    const float4* tg = (const float4*)d_in[3];

    fused_kernel<<<GRID, THREADS>>>(o0, o1, tg, o2, (float*)d_out);
}